// round 7
// baseline (speedup 1.0000x reference)
#include <cuda_runtime.h>
#include <math.h>

#define DIMC   1024
#define NHEADS 16
#define HDIM   64
#define BATCH  4
#define NQ     4096
#define NCTX   256

// Scratch (no allocations allowed) ------------------------------------------
__device__ float g_q [BATCH * NQ   * DIMC];  // 64 MB
__device__ float g_k [BATCH * NCTX * DIMC];  //  4 MB
__device__ float g_v [BATCH * NCTX * DIMC];  //  4 MB
__device__ float g_ao[BATCH * NQ   * DIMC];  // 64 MB

// ---------------------------------------------------------------------------
// SGEMM: C[M,N] = A[M,K] @ B[K,N] (+ bias). Row-major. 128x128x8 tiles,
// 256 threads, 8x8 per-thread microtile, float4 global/smem paths.
// M % 128 == 0, N % 128 == 0, K % 8 == 0 guaranteed by problem shapes.
// ---------------------------------------------------------------------------
__global__ __launch_bounds__(256) void sgemm128(
    const float* __restrict__ A, const float* __restrict__ Bm,
    const float* __restrict__ bias, float* __restrict__ C,
    int M, int N, int K)
{
    const int BM = 128, BN = 128, BK = 8;
    __shared__ float As[BK][BM];   // A stored transposed: As[k][m]
    __shared__ float Bs[BK][BN];

    const int t  = threadIdx.x;
    const int m0 = blockIdx.y * BM;
    const int n0 = blockIdx.x * BN;

    const int aRow  = t >> 1;          // 0..127
    const int aK4   = (t & 1) * 4;     // 0 or 4
    const int bRow  = t >> 5;          // 0..7
    const int bCol4 = (t & 31) * 4;    // 0..124
    const int ty = t >> 4;             // 0..15
    const int tx = t & 15;             // 0..15

    float acc[8][8];
#pragma unroll
    for (int m = 0; m < 8; m++)
#pragma unroll
        for (int n = 0; n < 8; n++) acc[m][n] = 0.f;

    const float* Ap = A  + (long)(m0 + aRow) * K + aK4;
    const float* Bp = Bm + (long)bRow * N + n0 + bCol4;

    for (int k0 = 0; k0 < K; k0 += BK) {
        float4 a4 = *(const float4*)(Ap + k0);
        As[aK4 + 0][aRow] = a4.x;
        As[aK4 + 1][aRow] = a4.y;
        As[aK4 + 2][aRow] = a4.z;
        As[aK4 + 3][aRow] = a4.w;
        float4 b4 = *(const float4*)(Bp + (long)k0 * N);
        *(float4*)&Bs[bRow][bCol4] = b4;
        __syncthreads();

#pragma unroll
        for (int kk = 0; kk < BK; kk++) {
            float4 a0 = *(const float4*)&As[kk][ty * 8];
            float4 a1 = *(const float4*)&As[kk][ty * 8 + 4];
            float4 b0 = *(const float4*)&Bs[kk][tx * 8];
            float4 b1 = *(const float4*)&Bs[kk][tx * 8 + 4];
            float ra[8] = {a0.x, a0.y, a0.z, a0.w, a1.x, a1.y, a1.z, a1.w};
            float rb[8] = {b0.x, b0.y, b0.z, b0.w, b1.x, b1.y, b1.z, b1.w};
#pragma unroll
            for (int m = 0; m < 8; m++)
#pragma unroll
                for (int n = 0; n < 8; n++) acc[m][n] += ra[m] * rb[n];
        }
        __syncthreads();
    }

    float bb[8];
#pragma unroll
    for (int n = 0; n < 8; n++) bb[n] = bias ? bias[n0 + tx * 8 + n] : 0.f;

#pragma unroll
    for (int m = 0; m < 8; m++) {
        int row = m0 + ty * 8 + m;
        float* Cp = C + (long)row * N + n0 + tx * 8;
        float4 r0, r1;
        r0.x = acc[m][0] + bb[0]; r0.y = acc[m][1] + bb[1];
        r0.z = acc[m][2] + bb[2]; r0.w = acc[m][3] + bb[3];
        r1.x = acc[m][4] + bb[4]; r1.y = acc[m][5] + bb[5];
        r1.z = acc[m][6] + bb[6]; r1.w = acc[m][7] + bb[7];
        *(float4*)(Cp)     = r0;
        *(float4*)(Cp + 4) = r1;
    }
}

// ---------------------------------------------------------------------------
// RMSNorm per head (+ RoPE for Q). One warp per (row, head); lane owns
// dims {lane, lane+32} of the 64-dim head.
// ---------------------------------------------------------------------------
__global__ __launch_bounds__(256) void rmsnorm_rope_q(
    float* __restrict__ q, const float* __restrict__ cs,
    const float* __restrict__ sn, const float* __restrict__ w)
{
    int gw   = (blockIdx.x * blockDim.x + threadIdx.x) >> 5;
    int lane = threadIdx.x & 31;
    int row  = gw >> 4;        // 0..16383
    int h    = gw & 15;

    float* p = q + (long)row * DIMC + h * HDIM;
    float v0 = p[lane], v1 = p[lane + 32];
    float ss = v0 * v0 + v1 * v1;
#pragma unroll
    for (int o = 16; o; o >>= 1) ss += __shfl_xor_sync(0xffffffffu, ss, o);
    float inv = rsqrtf(ss * (1.f / 64.f) + 1e-6f);

    float q0 = v0 * inv * w[lane];
    float q1 = v1 * inv * w[lane + 32];

    int n = row & (NQ - 1);
    float c0 = cs[n * HDIM + lane],      s0 = sn[n * HDIM + lane];
    float c1 = cs[n * HDIM + lane + 32], s1 = sn[n * HDIM + lane + 32];
    // rotate_half: d<32 -> -q[d+32]; d>=32 -> q[d-32]
    p[lane]      = q0 * c0 - q1 * s0;
    p[lane + 32] = q1 * c1 + q0 * s1;
}

__global__ __launch_bounds__(256) void rmsnorm_k(
    float* __restrict__ k, const float* __restrict__ w)
{
    int gw   = (blockIdx.x * blockDim.x + threadIdx.x) >> 5;
    int lane = threadIdx.x & 31;
    int row  = gw >> 4;        // 0..1023
    int h    = gw & 15;

    float* p = k + (long)row * DIMC + h * HDIM;
    float v0 = p[lane], v1 = p[lane + 32];
    float ss = v0 * v0 + v1 * v1;
#pragma unroll
    for (int o = 16; o; o >>= 1) ss += __shfl_xor_sync(0xffffffffu, ss, o);
    float inv = rsqrtf(ss * (1.f / 64.f) + 1e-6f);
    p[lane]      = v0 * inv * w[lane];
    p[lane + 32] = v1 * inv * w[lane + 32];
}

// ---------------------------------------------------------------------------
// Attention: block = (64 queries) x (one head) x (one batch). Nc=256 keys.
// smem: Qs[64][64], Kt[64][257] (transposed+padded: conflict-free),
//       Vs[256][64], S[64][256].
// Thread map for S and O: tx = lane (0..31), ty = warp (0..7).
// Warp w owns score rows {w, w+8, ..., w+56} through softmax AND the O pass,
// so only __syncwarp() is needed between those phases.
// ---------------------------------------------------------------------------
#define SM_QS 0
#define SM_KT (64 * 64)
#define SM_VS (SM_KT + 64 * 257)
#define SM_S  (SM_VS + 256 * 64)
#define SM_FLOATS (SM_S + 64 * 256)

__global__ __launch_bounds__(256) void attn_kernel(
    const float* __restrict__ q, const float* __restrict__ k,
    const float* __restrict__ v, float* __restrict__ ao)
{
    extern __shared__ float sm[];
    float* Qs = sm + SM_QS;
    float* Kt = sm + SM_KT;
    float* Vs = sm + SM_VS;
    float* S  = sm + SM_S;

    const int t  = threadIdx.x;
    const int nt = blockIdx.x, h = blockIdx.y, b = blockIdx.z;
    const int qrow0  = b * NQ + nt * 64;
    const int kvrow0 = b * NCTX;
    const int cbase  = h * HDIM;

    // load Q tile [64,64] (float4, coalesced)
    for (int i4 = t; i4 < 64 * 16; i4 += 256) {
        int i = i4 >> 4, d4 = (i4 & 15) << 2;
        *(float4*)&Qs[i * 64 + d4] =
            *(const float4*)&q[(long)(qrow0 + i) * DIMC + cbase + d4];
    }
    // load K transposed: Kt[d][j], padded row stride 257
    for (int idx = t; idx < 256 * 64; idx += 256) {
        int j = idx >> 6, d = idx & 63;
        Kt[d * 257 + j] = k[(long)(kvrow0 + j) * DIMC + cbase + d];
    }
    // load V [256,64]
    for (int i4 = t; i4 < 256 * 16; i4 += 256) {
        int j = i4 >> 4, d4 = (i4 & 15) << 2;
        *(float4*)&Vs[j * 64 + d4] =
            *(const float4*)&v[(long)(kvrow0 + j) * DIMC + cbase + d4];
    }
    __syncthreads();

    const int tx = t & 31, ty = t >> 5;

    // S = Q K^T * scale : per-thread 8x8 microtile (rows ty+8m, cols tx+32n)
    float acc[8][8];
#pragma unroll
    for (int m = 0; m < 8; m++)
#pragma unroll
        for (int n = 0; n < 8; n++) acc[m][n] = 0.f;

    for (int d = 0; d < 64; d++) {
        float ra[8], rb[8];
#pragma unroll
        for (int m = 0; m < 8; m++) ra[m] = Qs[(ty + 8 * m) * 64 + d];  // bcast
#pragma unroll
        for (int n = 0; n < 8; n++) rb[n] = Kt[d * 257 + tx + 32 * n]; // cf
#pragma unroll
        for (int m = 0; m < 8; m++)
#pragma unroll
            for (int n = 0; n < 8; n++) acc[m][n] += ra[m] * rb[n];
    }
    const float scale = 0.125f;  // 1/sqrt(64)
#pragma unroll
    for (int m = 0; m < 8; m++)
#pragma unroll
        for (int n = 0; n < 8; n++)
            S[(ty + 8 * m) * 256 + tx + 32 * n] = acc[m][n] * scale;
    __syncwarp();

    // softmax on warp-owned rows
    for (int r = 0; r < 8; r++) {
        int i = ty + 8 * r;
        float xs[8];
        float mx = -1e30f;
#pragma unroll
        for (int n = 0; n < 8; n++) {
            xs[n] = S[i * 256 + tx + 32 * n];
            mx = fmaxf(mx, xs[n]);
        }
#pragma unroll
        for (int o = 16; o; o >>= 1)
            mx = fmaxf(mx, __shfl_xor_sync(0xffffffffu, mx, o));
        float sum = 0.f;
#pragma unroll
        for (int n = 0; n < 8; n++) { xs[n] = __expf(xs[n] - mx); sum += xs[n]; }
#pragma unroll
        for (int o = 16; o; o >>= 1) sum += __shfl_xor_sync(0xffffffffu, sum, o);
        float invs = 1.f / sum;
#pragma unroll
        for (int n = 0; n < 8; n++) S[i * 256 + tx + 32 * n] = xs[n] * invs;
    }
    __syncwarp();

    // O = P @ V : thread owns rows {ty+8m}, dims {tx, tx+32}
    float o0[8], o1[8];
#pragma unroll
    for (int m = 0; m < 8; m++) { o0[m] = 0.f; o1[m] = 0.f; }
    for (int j = 0; j < 256; j++) {
        float va = Vs[j * 64 + tx];
        float vb = Vs[j * 64 + tx + 32];
#pragma unroll
        for (int m = 0; m < 8; m++) {
            float p = S[(ty + 8 * m) * 256 + j];  // bcast within warp
            o0[m] += p * va;
            o1[m] += p * vb;
        }
    }
#pragma unroll
    for (int m = 0; m < 8; m++) {
        long row = qrow0 + ty + 8 * m;
        ao[row * DIMC + cbase + tx]      = o0[m];
        ao[row * DIMC + cbase + tx + 32] = o1[m];
    }
}

// ---------------------------------------------------------------------------
extern "C" void kernel_launch(void* const* d_in, const int* in_sizes, int n_in,
                              void* d_out, int out_size)
{
    const float* x  = (const float*)d_in[0];
    const float* c  = (const float*)d_in[1];
    const float* rc = (const float*)d_in[2];
    const float* rs = (const float*)d_in[3];
    const float* Wq = (const float*)d_in[4];
    const float* Wk = (const float*)d_in[5];
    const float* Wv = (const float*)d_in[6];
    const float* Wo = (const float*)d_in[7];
    const float* bo = (const float*)d_in[8];
    const float* qw = (const float*)d_in[9];
    const float* kw = (const float*)d_in[10];
    float* out = (float*)d_out;

    float *q, *k, *v, *ao;
    cudaGetSymbolAddress((void**)&q,  g_q);
    cudaGetSymbolAddress((void**)&k,  g_k);
    cudaGetSymbolAddress((void**)&v,  g_v);
    cudaGetSymbolAddress((void**)&ao, g_ao);

    static bool attr_set = false;
    (void)attr_set;  // set every call; idempotent & cheap
    cudaFuncSetAttribute(attn_kernel, cudaFuncAttributeMaxDynamicSharedMemorySize,
                         SM_FLOATS * (int)sizeof(float));

    // Projections
    sgemm128<<<dim3(8, 128), 256>>>(x, Wq, nullptr, q, BATCH * NQ,   DIMC, DIMC);
    sgemm128<<<dim3(8, 8),   256>>>(c, Wk, nullptr, k, BATCH * NCTX, DIMC, DIMC);
    sgemm128<<<dim3(8, 8),   256>>>(c, Wv, nullptr, v, BATCH * NCTX, DIMC, DIMC);

    // Norm (+RoPE on Q)
    rmsnorm_rope_q<<<(BATCH * NQ * NHEADS) / 8, 256>>>(q, rc, rs, qw);
    rmsnorm_k<<<(BATCH * NCTX * NHEADS) / 8, 256>>>(k, kw);

    // Attention
    attn_kernel<<<dim3(NQ / 64, NHEADS, BATCH), 256,
                  SM_FLOATS * (int)sizeof(float)>>>(q, k, v, ao);

    // Output projection + bias
    sgemm128<<<dim3(8, 128), 256>>>(ao, Wo, bo, out, BATCH * NQ, DIMC, DIMC);
}

// round 8
// speedup vs baseline: 1.9821x; 1.9821x over previous
#include <cuda_runtime.h>
#include <math.h>

#define DIMC   1024
#define NHEADS 16
#define HDIM   64
#define BATCH  4
#define NQ     4096
#define NCTX   256

// Scratch (no allocations allowed) ------------------------------------------
__device__ float g_q [BATCH * NQ   * DIMC];  // 64 MB
__device__ float g_k [BATCH * NCTX * DIMC];  //  4 MB
__device__ float g_v [BATCH * NCTX * DIMC];  //  4 MB
__device__ float g_ao[BATCH * NQ   * DIMC];  // 64 MB

// ===========================================================================
// tf32 tensor-core GEMM: C[M,N] = A[M,K] @ B[K,N] (+bias)
// 128x128x32 CTA tile, 256 threads (2x4 warps, warp tile 64x32),
// mma.sync.aligned.m16n8k8.row.col.f32.tf32.tf32.f32, fp32 accumulate.
// smem: A [128][36] (rows 144B, 16B-aligned; frag reads conflict-free),
//       B [32][132] (rows 528B, 16B-aligned; frag reads <=2-way).
// Double-buffered cp.async.cg 16B pipeline.
// blockIdx.z selects (B0,C0) vs (B1,C1) so K and V proj share one launch.
// ===========================================================================
#define AST 36
#define BST 132
#define STAGE_F (128 * AST + 32 * BST)   // floats per stage = 8832
#define STAGE_B (STAGE_F * 4)            // 35328 bytes
#define GEMM_SMEM (2 * STAGE_B)          // 70656 bytes

__device__ __forceinline__ unsigned f2tf(float f) {
    unsigned r;
    asm("cvt.rna.tf32.f32 %0, %1;" : "=r"(r) : "f"(f));
    return r;
}

#define CPA16(saddr, gptr) \
    asm volatile("cp.async.cg.shared.global [%0], [%1], 16;" :: "r"(saddr), "l"(gptr))

__global__ __launch_bounds__(256) void gemm_tf32(
    const float* __restrict__ A,
    const float* __restrict__ B0, const float* __restrict__ B1,
    const float* __restrict__ bias,
    float* __restrict__ C0, float* __restrict__ C1,
    int M, int N, int K)
{
    extern __shared__ float sh[];
    const float* Bg = (blockIdx.z == 0) ? B0 : B1;
    float*       C  = (blockIdx.z == 0) ? C0 : C1;

    const int t    = threadIdx.x;
    const int lane = t & 31;
    const int w    = t >> 5;
    const int wm   = (w & 1) * 64;
    const int wn   = (w >> 1) * 32;
    const int m0   = blockIdx.y * 128;
    const int n0   = blockIdx.x * 128;

    const unsigned shu = (unsigned)__cvta_generic_to_shared(sh);

    float acc[4][4][4];
#pragma unroll
    for (int mt = 0; mt < 4; mt++)
#pragma unroll
        for (int nt = 0; nt < 4; nt++)
#pragma unroll
            for (int i = 0; i < 4; i++) acc[mt][nt][i] = 0.f;

    // ---- async load of one stage -----------------------------------------
    // A tile: 128 rows x 32 cols -> 1024 float4, 4 per thread
    // B tile:  32 rows x 128 cols -> 1024 float4, 4 per thread
#define ISSUE(s, k0)                                                          \
    {                                                                         \
        unsigned abase = shu + (s) * STAGE_B;                                 \
        unsigned bbase = abase + 128 * AST * 4;                               \
        _Pragma("unroll")                                                     \
        for (int j = 0; j < 4; j++) {                                         \
            int idx = t + j * 256;                                            \
            int r = idx >> 3, c4 = (idx & 7) << 2;                            \
            CPA16(abase + (unsigned)(r * AST + c4) * 4,                       \
                  A + (long)(m0 + r) * K + (k0) + c4);                        \
        }                                                                     \
        _Pragma("unroll")                                                     \
        for (int j = 0; j < 4; j++) {                                         \
            int idx = t + j * 256;                                            \
            int kk = idx >> 5, n4 = (idx & 31) << 2;                          \
            CPA16(bbase + (unsigned)(kk * BST + n4) * 4,                      \
                  Bg + (long)((k0) + kk) * N + n0 + n4);                      \
        }                                                                     \
        asm volatile("cp.async.commit_group;");                               \
    }

    const int niter = K >> 5;   // K/32
    ISSUE(0, 0);

    for (int it = 0; it < niter; it++) {
        if (it + 1 < niter) {
            ISSUE((it + 1) & 1, (it + 1) << 5);
            asm volatile("cp.async.wait_group 1;");
        } else {
            asm volatile("cp.async.wait_group 0;");
        }
        __syncthreads();

        const float* as = sh + (it & 1) * STAGE_F;
        const float* bs = as + 128 * AST;

#pragma unroll
        for (int kk = 0; kk < 32; kk += 8) {
            unsigned af[4][4], bf[4][2];
#pragma unroll
            for (int mt = 0; mt < 4; mt++) {
                int base = (wm + mt * 16 + (lane >> 2)) * AST + kk + (lane & 3);
                af[mt][0] = f2tf(as[base]);
                af[mt][1] = f2tf(as[base + 8 * AST]);
                af[mt][2] = f2tf(as[base + 4]);
                af[mt][3] = f2tf(as[base + 8 * AST + 4]);
            }
#pragma unroll
            for (int nt = 0; nt < 4; nt++) {
                int base = (kk + (lane & 3)) * BST + wn + nt * 8 + (lane >> 2);
                bf[nt][0] = f2tf(bs[base]);
                bf[nt][1] = f2tf(bs[base + 4 * BST]);
            }
#pragma unroll
            for (int mt = 0; mt < 4; mt++)
#pragma unroll
                for (int nt = 0; nt < 4; nt++) {
                    asm volatile(
                        "mma.sync.aligned.m16n8k8.row.col.f32.tf32.tf32.f32 "
                        "{%0,%1,%2,%3}, {%4,%5,%6,%7}, {%8,%9}, {%0,%1,%2,%3};"
                        : "+f"(acc[mt][nt][0]), "+f"(acc[mt][nt][1]),
                          "+f"(acc[mt][nt][2]), "+f"(acc[mt][nt][3])
                        : "r"(af[mt][0]), "r"(af[mt][1]),
                          "r"(af[mt][2]), "r"(af[mt][3]),
                          "r"(bf[nt][0]), "r"(bf[nt][1]));
                }
        }
        __syncthreads();
    }

    // ---- epilogue ---------------------------------------------------------
#pragma unroll
    for (int nt = 0; nt < 4; nt++) {
        int col = n0 + wn + nt * 8 + 2 * (lane & 3);
        float bb0 = bias ? bias[col]     : 0.f;
        float bb1 = bias ? bias[col + 1] : 0.f;
#pragma unroll
        for (int mt = 0; mt < 4; mt++) {
            int row = m0 + wm + mt * 16 + (lane >> 2);
            float2 r0, r1;
            r0.x = acc[mt][nt][0] + bb0; r0.y = acc[mt][nt][1] + bb1;
            r1.x = acc[mt][nt][2] + bb0; r1.y = acc[mt][nt][3] + bb1;
            *(float2*)&C[(long)row * N + col]       = r0;
            *(float2*)&C[(long)(row + 8) * N + col] = r1;
        }
    }
}

// ---------------------------------------------------------------------------
// RMSNorm per head (+ RoPE for Q). One warp per (row, head).
// ---------------------------------------------------------------------------
__global__ __launch_bounds__(256) void rmsnorm_rope_q(
    float* __restrict__ q, const float* __restrict__ cs,
    const float* __restrict__ sn, const float* __restrict__ w)
{
    int gw   = (blockIdx.x * blockDim.x + threadIdx.x) >> 5;
    int lane = threadIdx.x & 31;
    int row  = gw >> 4;
    int h    = gw & 15;

    float* p = q + (long)row * DIMC + h * HDIM;
    float v0 = p[lane], v1 = p[lane + 32];
    float ss = v0 * v0 + v1 * v1;
#pragma unroll
    for (int o = 16; o; o >>= 1) ss += __shfl_xor_sync(0xffffffffu, ss, o);
    float inv = rsqrtf(ss * (1.f / 64.f) + 1e-6f);

    float q0 = v0 * inv * w[lane];
    float q1 = v1 * inv * w[lane + 32];

    int n = row & (NQ - 1);
    float c0 = cs[n * HDIM + lane],      s0 = sn[n * HDIM + lane];
    float c1 = cs[n * HDIM + lane + 32], s1 = sn[n * HDIM + lane + 32];
    p[lane]      = q0 * c0 - q1 * s0;
    p[lane + 32] = q1 * c1 + q0 * s1;
}

__global__ __launch_bounds__(256) void rmsnorm_k(
    float* __restrict__ k, const float* __restrict__ w)
{
    int gw   = (blockIdx.x * blockDim.x + threadIdx.x) >> 5;
    int lane = threadIdx.x & 31;
    int row  = gw >> 4;
    int h    = gw & 15;

    float* p = k + (long)row * DIMC + h * HDIM;
    float v0 = p[lane], v1 = p[lane + 32];
    float ss = v0 * v0 + v1 * v1;
#pragma unroll
    for (int o = 16; o; o >>= 1) ss += __shfl_xor_sync(0xffffffffu, ss, o);
    float inv = rsqrtf(ss * (1.f / 64.f) + 1e-6f);
    p[lane]      = v0 * inv * w[lane];
    p[lane + 32] = v1 * inv * w[lane + 32];
}

// ---------------------------------------------------------------------------
// Attention (fp32): block = 64 queries x 1 head x 1 batch. Nc=256 keys.
// ---------------------------------------------------------------------------
#define SM_QS 0
#define SM_KT (64 * 64)
#define SM_VS (SM_KT + 64 * 257)
#define SM_S  (SM_VS + 256 * 64)
#define SM_FLOATS (SM_S + 64 * 256)

__global__ __launch_bounds__(256) void attn_kernel(
    const float* __restrict__ q, const float* __restrict__ k,
    const float* __restrict__ v, float* __restrict__ ao)
{
    extern __shared__ float sm[];
    float* Qs = sm + SM_QS;
    float* Kt = sm + SM_KT;
    float* Vs = sm + SM_VS;
    float* S  = sm + SM_S;

    const int t  = threadIdx.x;
    const int nt = blockIdx.x, h = blockIdx.y, b = blockIdx.z;
    const int qrow0  = b * NQ + nt * 64;
    const int kvrow0 = b * NCTX;
    const int cbase  = h * HDIM;

    for (int i4 = t; i4 < 64 * 16; i4 += 256) {
        int i = i4 >> 4, d4 = (i4 & 15) << 2;
        *(float4*)&Qs[i * 64 + d4] =
            *(const float4*)&q[(long)(qrow0 + i) * DIMC + cbase + d4];
    }
    for (int idx = t; idx < 256 * 64; idx += 256) {
        int j = idx >> 6, d = idx & 63;
        Kt[d * 257 + j] = k[(long)(kvrow0 + j) * DIMC + cbase + d];
    }
    for (int i4 = t; i4 < 256 * 16; i4 += 256) {
        int j = i4 >> 4, d4 = (i4 & 15) << 2;
        *(float4*)&Vs[j * 64 + d4] =
            *(const float4*)&v[(long)(kvrow0 + j) * DIMC + cbase + d4];
    }
    __syncthreads();

    const int tx = t & 31, ty = t >> 5;

    float acc[8][8];
#pragma unroll
    for (int m = 0; m < 8; m++)
#pragma unroll
        for (int n = 0; n < 8; n++) acc[m][n] = 0.f;

    for (int d = 0; d < 64; d++) {
        float ra[8], rb[8];
#pragma unroll
        for (int m = 0; m < 8; m++) ra[m] = Qs[(ty + 8 * m) * 64 + d];
#pragma unroll
        for (int n = 0; n < 8; n++) rb[n] = Kt[d * 257 + tx + 32 * n];
#pragma unroll
        for (int m = 0; m < 8; m++)
#pragma unroll
            for (int n = 0; n < 8; n++) acc[m][n] += ra[m] * rb[n];
    }
    const float scale = 0.125f;
#pragma unroll
    for (int m = 0; m < 8; m++)
#pragma unroll
        for (int n = 0; n < 8; n++)
            S[(ty + 8 * m) * 256 + tx + 32 * n] = acc[m][n] * scale;
    __syncwarp();

    for (int r = 0; r < 8; r++) {
        int i = ty + 8 * r;
        float xs[8];
        float mx = -1e30f;
#pragma unroll
        for (int n = 0; n < 8; n++) {
            xs[n] = S[i * 256 + tx + 32 * n];
            mx = fmaxf(mx, xs[n]);
        }
#pragma unroll
        for (int o = 16; o; o >>= 1)
            mx = fmaxf(mx, __shfl_xor_sync(0xffffffffu, mx, o));
        float sum = 0.f;
#pragma unroll
        for (int n = 0; n < 8; n++) { xs[n] = __expf(xs[n] - mx); sum += xs[n]; }
#pragma unroll
        for (int o = 16; o; o >>= 1) sum += __shfl_xor_sync(0xffffffffu, sum, o);
        float invs = 1.f / sum;
#pragma unroll
        for (int n = 0; n < 8; n++) S[i * 256 + tx + 32 * n] = xs[n] * invs;
    }
    __syncwarp();

    float o0[8], o1[8];
#pragma unroll
    for (int m = 0; m < 8; m++) { o0[m] = 0.f; o1[m] = 0.f; }
    for (int j = 0; j < 256; j++) {
        float va = Vs[j * 64 + tx];
        float vb = Vs[j * 64 + tx + 32];
#pragma unroll
        for (int m = 0; m < 8; m++) {
            float p = S[(ty + 8 * m) * 256 + j];
            o0[m] += p * va;
            o1[m] += p * vb;
        }
    }
#pragma unroll
    for (int m = 0; m < 8; m++) {
        long row = qrow0 + ty + 8 * m;
        ao[row * DIMC + cbase + tx]      = o0[m];
        ao[row * DIMC + cbase + tx + 32] = o1[m];
    }
}

// ---------------------------------------------------------------------------
extern "C" void kernel_launch(void* const* d_in, const int* in_sizes, int n_in,
                              void* d_out, int out_size)
{
    const float* x  = (const float*)d_in[0];
    const float* c  = (const float*)d_in[1];
    const float* rc = (const float*)d_in[2];
    const float* rs = (const float*)d_in[3];
    const float* Wq = (const float*)d_in[4];
    const float* Wk = (const float*)d_in[5];
    const float* Wv = (const float*)d_in[6];
    const float* Wo = (const float*)d_in[7];
    const float* bo = (const float*)d_in[8];
    const float* qw = (const float*)d_in[9];
    const float* kw = (const float*)d_in[10];
    float* out = (float*)d_out;

    float *q, *k, *v, *ao;
    cudaGetSymbolAddress((void**)&q,  g_q);
    cudaGetSymbolAddress((void**)&k,  g_k);
    cudaGetSymbolAddress((void**)&v,  g_v);
    cudaGetSymbolAddress((void**)&ao, g_ao);

    cudaFuncSetAttribute(gemm_tf32, cudaFuncAttributeMaxDynamicSharedMemorySize,
                         GEMM_SMEM);
    cudaFuncSetAttribute(attn_kernel, cudaFuncAttributeMaxDynamicSharedMemorySize,
                         SM_FLOATS * (int)sizeof(float));

    // Q projection: [16384,1024] @ [1024,1024]
    gemm_tf32<<<dim3(8, 128, 1), 256, GEMM_SMEM>>>(
        x, Wq, Wq, nullptr, q, q, BATCH * NQ, DIMC, DIMC);
    // K and V projections fused into one launch via blockIdx.z
    gemm_tf32<<<dim3(8, 8, 2), 256, GEMM_SMEM>>>(
        c, Wk, Wv, nullptr, k, v, BATCH * NCTX, DIMC, DIMC);

    // Norm (+RoPE on Q)
    rmsnorm_rope_q<<<(BATCH * NQ * NHEADS) / 8, 256>>>(q, rc, rs, qw);
    rmsnorm_k<<<(BATCH * NCTX * NHEADS) / 8, 256>>>(k, kw);

    // Attention (fp32)
    attn_kernel<<<dim3(NQ / 64, NHEADS, BATCH), 256,
                  SM_FLOATS * (int)sizeof(float)>>>(q, k, v, ao);

    // Output projection + bias
    gemm_tf32<<<dim3(8, 128, 1), 256, GEMM_SMEM>>>(
        ao, Wo, Wo, bo, out, out, BATCH * NQ, DIMC, DIMC);
}